// round 9
// baseline (speedup 1.0000x reference)
#include <cuda_runtime.h>
#include <cuda_fp16.h>
#include <cfloat>
#include <cstdint>

// ===========================================================================
// SimpleAttention 4096x4096, sm_103 legacy tensor path, INT8 IMMA.
//
//   x = feats/64;  sims = x x^T;  attn = softmax(sims, diag=-inf);
//   out = attn @ x^T.
//
// Numerics: sims ~ N(0, 1/64^2) => attn entries are all within ~7% of 1/n.
// Decompose with baseline B (B_ij = 1/(n-1) off-diag, 0 on diag):
//   out[i][j] = (S_j - x[j][i])/(n-1)  +  (D~ @ x^T)[i][j]
// where S_j = sum_k x[j][k] and D~ = attn - B has diag 0 and entries ~±1.5e-5.
// The D~-GEMM tolerates int8 (per-row scale); GEMM1 (sims) also int8:
//   sims = qx^2 * (Xq Xq^T),  exact s32 accumulation.
// mma.sync.m16n8k32.s8 runs at 2x fp16 rate; k32-s8 tiles are byte-identical
// to k16-fp16 tiles so all ldmatrix addressing carries over unchanged.
// ===========================================================================

constexpr int NMAT = 4096;
constexpr int NSTEPS = 32;            // 4096 / 128 s8 per stage row
constexpr int TILEB = 128 * 128;      // 16 KB per operand tile (128B rows)
constexpr int STAGE = 2 * TILEB;      // 32 KB
constexpr int NSTAGE = 3;             // 96 KB smem
constexpr int SMEM_TOTAL = NSTAGE * STAGE;
constexpr int TPAD = 132;             // mirror transpose row stride (floats)

constexpr float QX    = 0.09f / 127.0f;     // |x| <= ~0.086 < 0.09
constexpr float QX2   = QX * QX;
constexpr float INVN1 = 1.0f / 4095.0f;     // 1/(n-1)

// ---- device scratch (allocation-free) -------------------------------------
__device__ int8_t g_xq[(size_t)NMAT * NMAT];    // int8 x
__device__ __half g_xt[(size_t)NMAT * NMAT];    // fp16 x^T (epilogue term)
__device__ __half g_sims[(size_t)NMAT * NMAT];  // fp16 sims
__device__ int8_t g_dq[(size_t)NMAT * NMAT];    // int8 D~
__device__ float  g_qd[NMAT];                   // per-row D~ scales
__device__ float  g_S[NMAT];                    // row sums of x

// ---- helpers --------------------------------------------------------------
#define SWZ(o) ((o) ^ (((o) >> 3) & 0x70))

__device__ __forceinline__ uint32_t smem_u32(const void* p) {
    uint32_t a;
    asm("{ .reg .u64 t; cvta.to.shared.u64 t, %1; cvt.u32.u64 %0, t; }"
        : "=r"(a) : "l"(p));
    return a;
}
__device__ __forceinline__ void cp_async16(uint32_t dst, const void* src) {
    asm volatile("cp.async.cg.shared.global [%0], [%1], 16;"
                 :: "r"(dst), "l"(src));
}
__device__ __forceinline__ void cp_commit() {
    asm volatile("cp.async.commit_group;" ::: "memory");
}
template <int N>
__device__ __forceinline__ void cp_wait() {
    asm volatile("cp.async.wait_group %0;" :: "n"(N) : "memory");
}
__device__ __forceinline__ void ldsm_x4(uint32_t addr, uint32_t r[4]) {
    asm volatile("ldmatrix.sync.aligned.m8n8.x4.shared.b16 {%0,%1,%2,%3}, [%4];"
                 : "=r"(r[0]), "=r"(r[1]), "=r"(r[2]), "=r"(r[3]) : "r"(addr));
}
__device__ __forceinline__ void mma_s8(int d[4], const uint32_t a[4],
                                       uint32_t b0, uint32_t b1) {
    asm volatile(
        "mma.sync.aligned.m16n8k32.row.col.s32.s8.s8.s32 "
        "{%0,%1,%2,%3}, {%4,%5,%6,%7}, {%8,%9}, {%0,%1,%2,%3};"
        : "+r"(d[0]), "+r"(d[1]), "+r"(d[2]), "+r"(d[3])
        : "r"(a[0]), "r"(a[1]), "r"(a[2]), "r"(a[3]), "r"(b0), "r"(b1));
}
__device__ __forceinline__ int8_t q127(float v) {
    int q = __float2int_rn(v);
    q = max(-127, min(127, q));
    return (int8_t)q;
}

// ===========================================================================
// INT8 GEMM: acc = A @ B^T over int8, s32 accum.  A[m][k], B[n][k] row-major.
// MODE 1: C = sims fp16 = QX2 * acc; symmetric -> only by<=bx, mirror-write.
// MODE 2: C = out fp32 = qd[row]*QX*acc + (S[col] - xT[row][col])*INVN1.
// CTA tile 128x128, 4 warps (64x64 warp tiles), 3-stage cp.async, 2 CTA/SM.
// ===========================================================================
template <int MODE>
__global__ __launch_bounds__(128, 2)
void gemm_s8(const int8_t* __restrict__ A, const int8_t* __restrict__ B,
             void* __restrict__ Cout,
             const float* __restrict__ qd, const float* __restrict__ Sv,
             const __half* __restrict__ xt)
{
    if (MODE == 1 && blockIdx.y > blockIdx.x) return;  // lower triangle: skip

    extern __shared__ char smem[];
    const uint32_t sbase = smem_u32(smem);

    const int tid  = threadIdx.x;
    const int warp = tid >> 5;
    const int lane = tid & 31;
    const int wm   = (warp & 1) * 64;
    const int wn   = (warp >> 1) * 64;
    const int rowBase = blockIdx.y * 128;
    const int colBase = blockIdx.x * 128;

    const size_t rowBy = (size_t)NMAT;  // bytes per gmem row (int8)
    const char* gA = (const char*)(A + (size_t)rowBase * NMAT);
    const char* gB = (const char*)(B + (size_t)colBase * NMAT);

    // ldmatrix addressing (byte-identical to the fp16-k16 layout)
    const int mA  = (lane & 7) + ((lane >> 3) & 1) * 8;
    const int kAo = ((lane >> 4) & 1) * 16;
    const int nB  = (lane & 7) + ((lane >> 4) & 1) * 8;
    const int kBo = ((lane >> 3) & 1) * 16;

    int acc[4][8][4];
#pragma unroll
    for (int i = 0; i < 4; i++)
#pragma unroll
        for (int j = 0; j < 8; j++)
#pragma unroll
            for (int t = 0; t < 4; t++) acc[i][j][t] = 0;

    auto load_stage = [&](int kt) {
        if (kt < NSTEPS) {
            const uint32_t st = sbase + (kt % NSTAGE) * STAGE;
            const size_t kOff = (size_t)kt * 128;  // 128 s8 = 128 bytes
#pragma unroll
            for (int l = 0; l < 8; l++) {
                const int i = tid + l * 128;
                const int r = i >> 3, c = (i & 7) << 4;
                cp_async16(st + SWZ(r * 128 + c),
                           gA + (size_t)r * rowBy + kOff + c);
            }
#pragma unroll
            for (int l = 0; l < 8; l++) {
                const int i = tid + l * 128;
                const int r = i >> 3, c = (i & 7) << 4;
                cp_async16(st + TILEB + SWZ(r * 128 + c),
                           gB + (size_t)r * rowBy + kOff + c);
            }
        }
        cp_commit();
    };

    load_stage(0);
    load_stage(1);

    for (int kt = 0; kt < NSTEPS; kt++) {
        cp_wait<NSTAGE - 2>();
        __syncthreads();
        load_stage(kt + NSTAGE - 1);

        const uint32_t st = sbase + (kt % NSTAGE) * STAGE;
#pragma unroll
        for (int ck = 0; ck < 4; ck++) {   // 4 x k32 chunks (32B each)
            const int kb = ck * 32;

            uint32_t a[4][4];
#pragma unroll
            for (int mi = 0; mi < 4; mi++)
                ldsm_x4(st + SWZ((wm + mi * 16 + mA) * 128 + kb + kAo), a[mi]);
            uint32_t b[4][4];
#pragma unroll
            for (int nb = 0; nb < 4; nb++)
                ldsm_x4(st + TILEB + SWZ((wn + nb * 16 + nB) * 128 + kb + kBo),
                        b[nb]);

#pragma unroll
            for (int mi = 0; mi < 4; mi++)
#pragma unroll
                for (int nb = 0; nb < 4; nb++)
#pragma unroll
                    for (int h = 0; h < 2; h++)
                        mma_s8(acc[mi][nb * 2 + h], a[mi],
                               b[nb][2 * h], b[nb][2 * h + 1]);
        }
    }

    const int rq = lane >> 2, cq = (lane & 3) * 2;

    if (MODE == 1) {
        __half* C = (__half*)Cout;
        // sims = QX2 * acc, fp16
#pragma unroll
        for (int mi = 0; mi < 4; mi++) {
            const int row0 = rowBase + wm + mi * 16 + rq;
#pragma unroll
            for (int nj = 0; nj < 8; nj++) {
                const int col = colBase + wn + nj * 8 + cq;
                *(__half2*)&C[(size_t)row0 * NMAT + col] =
                    __floats2half2_rn(acc[mi][nj][0] * QX2, acc[mi][nj][1] * QX2);
                *(__half2*)&C[(size_t)(row0 + 8) * NMAT + col] =
                    __floats2half2_rn(acc[mi][nj][2] * QX2, acc[mi][nj][3] * QX2);
            }
        }
        // mirror write for off-diagonal tiles
        if (blockIdx.x != blockIdx.y) {
            __syncthreads();
            float* T = (float*)smem;  // [128][TPAD] floats = 67.6 KB
#pragma unroll
            for (int mi = 0; mi < 4; mi++) {
                const int r0 = wm + mi * 16 + rq;
#pragma unroll
                for (int nj = 0; nj < 8; nj++) {
                    const int c0 = wn + nj * 8 + cq;
                    T[(c0 + 0) * TPAD + r0]     = acc[mi][nj][0] * QX2;
                    T[(c0 + 1) * TPAD + r0]     = acc[mi][nj][1] * QX2;
                    T[(c0 + 0) * TPAD + r0 + 8] = acc[mi][nj][2] * QX2;
                    T[(c0 + 1) * TPAD + r0 + 8] = acc[mi][nj][3] * QX2;
                }
            }
            __syncthreads();
#pragma unroll 4
            for (int rb = 0; rb < 128; rb += 4) {
                const int rr = rb + warp;
                const float4 v = *(const float4*)&T[rr * TPAD + (lane << 2)];
                __half2 h0 = __floats2half2_rn(v.x, v.y);
                __half2 h1 = __floats2half2_rn(v.z, v.w);
                *(uint2*)&C[(size_t)(colBase + rr) * NMAT + rowBase + (lane << 2)] =
                    make_uint2(*(uint32_t*)&h0, *(uint32_t*)&h1);
            }
        }
    } else {
        float* C = (float*)Cout;
        // out = qd[row]*QX*acc + (S[col] - xT[row][col]) * INVN1
#pragma unroll
        for (int mi = 0; mi < 4; mi++) {
            const int row0 = rowBase + wm + mi * 16 + rq;
            const float sc0 = qd[row0] * QX;
            const float sc1 = qd[row0 + 8] * QX;
#pragma unroll
            for (int nj = 0; nj < 8; nj++) {
                const int col = colBase + wn + nj * 8 + cq;
                const float s0 = Sv[col], s1 = Sv[col + 1];
                const float2 xt0 =
                    __half22float2(*(const __half2*)&xt[(size_t)row0 * NMAT + col]);
                const float2 xt1 =
                    __half22float2(*(const __half2*)&xt[(size_t)(row0 + 8) * NMAT + col]);
                *(float2*)&C[(size_t)row0 * NMAT + col] = make_float2(
                    sc0 * acc[mi][nj][0] + (s0 - xt0.x) * INVN1,
                    sc0 * acc[mi][nj][1] + (s1 - xt0.y) * INVN1);
                *(float2*)&C[(size_t)(row0 + 8) * NMAT + col] = make_float2(
                    sc1 * acc[mi][nj][2] + (s0 - xt1.x) * INVN1,
                    sc1 * acc[mi][nj][3] + (s1 - xt1.y) * INVN1);
            }
        }
    }
}

// ===========================================================================
// P1: feats -> int8 Xq (row-major) + fp16 x^T (transposed), 64x64 tiles.
// ===========================================================================
__global__ __launch_bounds__(256)
void quant_transpose(const float* __restrict__ feats,
                     int8_t* __restrict__ xq, __half* __restrict__ xt)
{
    __shared__ float T[64][65];
    const int tileR = blockIdx.y * 64, tileC = blockIdx.x * 64;
    const int r0 = threadIdx.x >> 4;           // 0..15
    const int c4 = (threadIdx.x & 15) << 2;    // 0..60

#pragma unroll
    for (int rr = 0; rr < 64; rr += 16) {
        const int r = r0 + rr;
        const float4 v =
            *(const float4*)&feats[(size_t)(tileR + r) * NMAT + tileC + c4];
        const float x0 = v.x * (1.0f / 64.0f), x1 = v.y * (1.0f / 64.0f);
        const float x2 = v.z * (1.0f / 64.0f), x3 = v.w * (1.0f / 64.0f);
        T[r][c4 + 0] = x0; T[r][c4 + 1] = x1;
        T[r][c4 + 2] = x2; T[r][c4 + 3] = x3;
        char4 q;
        q.x = q127(x0 * (1.0f / QX)); q.y = q127(x1 * (1.0f / QX));
        q.z = q127(x2 * (1.0f / QX)); q.w = q127(x3 * (1.0f / QX));
        *(char4*)&xq[(size_t)(tileR + r) * NMAT + tileC + c4] = q;
    }
    __syncthreads();
#pragma unroll
    for (int rr = 0; rr < 64; rr += 16) {
        const int r = r0 + rr;   // local row of x^T tile
        __half2 h0 = __floats2half2_rn(T[c4 + 0][r], T[c4 + 1][r]);
        __half2 h1 = __floats2half2_rn(T[c4 + 2][r], T[c4 + 3][r]);
        *(uint2*)&xt[(size_t)(tileC + r) * NMAT + tileR + c4] =
            make_uint2(*(uint32_t*)&h0, *(uint32_t*)&h1);
    }
}

// ===========================================================================
// P2: S[j] = sum_k feats[j][k] / 64   (one block per row)
// ===========================================================================
__global__ __launch_bounds__(256)
void rowsum(const float* __restrict__ feats, float* __restrict__ Sv)
{
    const int row = blockIdx.x;
    const int tid = threadIdx.x;
    const float4* p = (const float4*)(feats + (size_t)row * NMAT);
    float s = 0.0f;
#pragma unroll
    for (int i = 0; i < 4; i++) {
        const float4 v = p[tid + i * 256];
        s += (v.x + v.y) + (v.z + v.w);
    }
    __shared__ float red[256];
    red[tid] = s;
    __syncthreads();
#pragma unroll
    for (int st = 128; st > 0; st >>= 1) {
        if (tid < st) red[tid] += red[tid + st];
        __syncthreads();
    }
    if (tid == 0) Sv[row] = red[0] * (1.0f / 64.0f);
}

// ===========================================================================
// Softmax rows (diag masked) -> D~ int8 with per-row scale qd.
//   attn = softmax(sims); D~ = attn - INVN1 off-diag, 0 on diag.
// ===========================================================================
__global__ __launch_bounds__(256)
void softmax_rows(const __half* __restrict__ S, int8_t* __restrict__ Dq,
                  float* __restrict__ qd)
{
    const int row = blockIdx.x;
    const int tid = threadIdx.x;
    const __half2* p = (const __half2*)(S + (size_t)row * NMAT);

    float v[16];
    float m = -FLT_MAX;
#pragma unroll
    for (int i = 0; i < 8; i++) {
        const int j2 = tid + i * 256;
        const float2 f = __half22float2(p[j2]);
        v[2 * i] = f.x; v[2 * i + 1] = f.y;
        const int j = 2 * j2;
        if (j != row)     m = fmaxf(m, f.x);
        if (j + 1 != row) m = fmaxf(m, f.y);
    }

    __shared__ float red[256];
    red[tid] = m;
    __syncthreads();
#pragma unroll
    for (int st = 128; st > 0; st >>= 1) {
        if (tid < st) red[tid] = fmaxf(red[tid], red[tid + st]);
        __syncthreads();
    }
    m = red[0];
    __syncthreads();

    float sum = 0.0f;
#pragma unroll
    for (int i = 0; i < 8; i++) {
        const int j = 2 * (tid + i * 256);
        const float e0 = (j == row)     ? 0.0f : __expf(v[2 * i] - m);
        const float e1 = (j + 1 == row) ? 0.0f : __expf(v[2 * i + 1] - m);
        v[2 * i] = e0; v[2 * i + 1] = e1;
        sum += e0 + e1;
    }
    red[tid] = sum;
    __syncthreads();
#pragma unroll
    for (int st = 128; st > 0; st >>= 1) {
        if (tid < st) red[tid] += red[tid + st];
        __syncthreads();
    }
    const float inv = 1.0f / red[0];
    __syncthreads();

    // D~ values and row max|D~|
    float rmax = 0.0f;
#pragma unroll
    for (int i = 0; i < 16; i++) {
        const int j = (tid + (i >> 1) * 256) * 2 + (i & 1);
        float d = (j == row) ? 0.0f : (v[i] * inv - INVN1);
        v[i] = d;
        rmax = fmaxf(rmax, fabsf(d));
    }
    red[tid] = rmax;
    __syncthreads();
#pragma unroll
    for (int st = 128; st > 0; st >>= 1) {
        if (tid < st) red[tid] = fmaxf(red[tid], red[tid + st]);
        __syncthreads();
    }
    const float rm = fmaxf(red[0], 1e-30f);
    const float invq = 127.0f / rm;

    char2* drow = (char2*)(Dq + (size_t)row * NMAT);
#pragma unroll
    for (int i = 0; i < 8; i++) {
        const int j2 = tid + i * 256;
        char2 c;
        c.x = q127(v[2 * i] * invq);
        c.y = q127(v[2 * i + 1] * invq);
        drow[j2] = c;
    }
    if (tid == 0) qd[row] = rm * (1.0f / 127.0f);
}

// ===========================================================================
extern "C" void kernel_launch(void* const* d_in, const int* in_sizes, int n_in,
                              void* d_out, int out_size)
{
    const float* feats = (const float*)d_in[0];
    float* out = (float*)d_out;

    int8_t *xq, *dq;
    __half *xt, *sims;
    float *qdv, *Sv;
    cudaGetSymbolAddress((void**)&xq, g_xq);
    cudaGetSymbolAddress((void**)&xt, g_xt);
    cudaGetSymbolAddress((void**)&sims, g_sims);
    cudaGetSymbolAddress((void**)&dq, g_dq);
    cudaGetSymbolAddress((void**)&qdv, g_qd);
    cudaGetSymbolAddress((void**)&Sv, g_S);

    cudaFuncSetAttribute((void*)gemm_s8<1>,
                         cudaFuncAttributeMaxDynamicSharedMemorySize, SMEM_TOTAL);
    cudaFuncSetAttribute((void*)gemm_s8<2>,
                         cudaFuncAttributeMaxDynamicSharedMemorySize, SMEM_TOTAL);

    // 1) quantize x to int8 + build fp16 x^T;  2) row sums of x
    quant_transpose<<<dim3(64, 64), 256>>>(feats, xq, xt);
    rowsum<<<NMAT, 256>>>(feats, Sv);

    dim3 grid(NMAT / 128, NMAT / 128);  // (32, 32)

    // 3) sims = QX2 * (Xq Xq^T)  (symmetric: upper tiles + mirror), fp16
    gemm_s8<1><<<grid, 128, SMEM_TOTAL>>>(xq, xq, sims, nullptr, nullptr, nullptr);

    // 4) softmax rows -> D~ int8 + per-row scales
    softmax_rows<<<NMAT, 256>>>(sims, dq, qdv);

    // 5) out = qd*QX*(Dq Xq^T) + (S - x^T) * INVN1
    gemm_s8<2><<<grid, 128, SMEM_TOTAL>>>(dq, xq, out, qdv, Sv, xt);
}

// round 13
// speedup vs baseline: 2.9421x; 2.9421x over previous
#include <cuda_runtime.h>
#include <cuda_fp16.h>
#include <cfloat>
#include <cstdint>

// ===========================================================================
// SimpleAttention 4096x4096, sm_103 legacy tensor path (tcgen05 unavailable on
// the plain sm_103 PTX target; legacy s8 IMMA measured ~4x slow -> fp16 HMMA).
//   sims = feats @ feats^T / 4096   GEMM1: fp16 inputs, fp16 ACCUM (rate
//                                   probe), symmetric: upper tiles + mirror.
//   attn = softmax(sims, diag masked) -> fp16
//   out  = attn @ feats^T / 64      GEMM2: fp16 inputs, fp32 accum (R8 path).
// GEMM: C = alpha * A @ B^T, A[m][k], B[n][k] row-major fp16.
// CTA tile 128x128 (4 warps, 64x64 warp tile), BK=64, 3-stage cp.async,
// 2 CTAs/SM.
// ===========================================================================

constexpr int NMAT = 4096;
constexpr int NSTEPS = 64;                // 4096 / 64
constexpr int TILEB = 128 * 128;          // bytes per operand tile (128B rows)
constexpr int STAGE = 2 * TILEB;          // 32 KB
constexpr int NSTAGE = 3;                 // 96 KB smem
constexpr int SMEM_TOTAL = NSTAGE * STAGE;
constexpr int TPAD = 132;                 // transpose buffer row stride (floats)

// ---- device scratch (allocation-free) -------------------------------------
__device__ __half g_sims[(size_t)NMAT * NMAT];  // fp16 sims
__device__ __half g_xh[(size_t)NMAT * NMAT];    // fp16(feats)
__device__ __half g_ah[(size_t)NMAT * NMAT];    // fp16(attn)

// ---- helpers --------------------------------------------------------------
#define SWZ(o) ((o) ^ (((o) >> 3) & 0x70))

__device__ __forceinline__ uint32_t smem_u32(const void* p) {
    uint32_t a;
    asm("{ .reg .u64 t; cvta.to.shared.u64 t, %1; cvt.u32.u64 %0, t; }"
        : "=r"(a) : "l"(p));
    return a;
}
__device__ __forceinline__ void cp_async16(uint32_t dst, const void* src) {
    asm volatile("cp.async.cg.shared.global [%0], [%1], 16;"
                 :: "r"(dst), "l"(src));
}
__device__ __forceinline__ void cp_commit() {
    asm volatile("cp.async.commit_group;" ::: "memory");
}
template <int N>
__device__ __forceinline__ void cp_wait() {
    asm volatile("cp.async.wait_group %0;" :: "n"(N) : "memory");
}
__device__ __forceinline__ void ldsm_x4(uint32_t addr, uint32_t r[4]) {
    asm volatile("ldmatrix.sync.aligned.m8n8.x4.shared.b16 {%0,%1,%2,%3}, [%4];"
                 : "=r"(r[0]), "=r"(r[1]), "=r"(r[2]), "=r"(r[3]) : "r"(addr));
}
// fp32 accumulators
__device__ __forceinline__ void mma_f16(float d[4], const uint32_t a[4],
                                        uint32_t b0, uint32_t b1) {
    asm volatile(
        "mma.sync.aligned.m16n8k16.row.col.f32.f16.f16.f32 "
        "{%0,%1,%2,%3}, {%4,%5,%6,%7}, {%8,%9}, {%0,%1,%2,%3};"
        : "+f"(d[0]), "+f"(d[1]), "+f"(d[2]), "+f"(d[3])
        : "r"(a[0]), "r"(a[1]), "r"(a[2]), "r"(a[3]), "r"(b0), "r"(b1));
}
// fp16 accumulators (rate probe; 2 b32 regs hold 4 halves)
__device__ __forceinline__ void mma_f16h(uint32_t d[2], const uint32_t a[4],
                                         uint32_t b0, uint32_t b1) {
    asm volatile(
        "mma.sync.aligned.m16n8k16.row.col.f16.f16.f16.f16 "
        "{%0,%1}, {%2,%3,%4,%5}, {%6,%7}, {%0,%1};"
        : "+r"(d[0]), "+r"(d[1])
        : "r"(a[0]), "r"(a[1]), "r"(a[2]), "r"(a[3]), "r"(b0), "r"(b1));
}

// ===========================================================================
// GEMM1 (symmetric): sims = alpha * A A^T, fp16 accum, fp16 out.
// Only tiles by <= bx computed; off-diagonal tiles mirror-written transposed.
// ===========================================================================
__global__ __launch_bounds__(128, 2)
void gemm_sym(const __half* __restrict__ A, __half* __restrict__ C, float alpha)
{
    if (blockIdx.y > blockIdx.x) return;

    extern __shared__ char smem[];
    const uint32_t sbase = smem_u32(smem);

    const int tid  = threadIdx.x;
    const int warp = tid >> 5;
    const int lane = tid & 31;
    const int wm   = (warp & 1) * 64;
    const int wn   = (warp >> 1) * 64;
    const int rowBase = blockIdx.y * 128;
    const int colBase = blockIdx.x * 128;

    const size_t rowB = (size_t)NMAT * 2;
    const char* gA = (const char*)(A + (size_t)rowBase * NMAT);
    const char* gB = (const char*)(A + (size_t)colBase * NMAT);

    const int mA  = (lane & 7) + ((lane >> 3) & 1) * 8;
    const int kAo = ((lane >> 4) & 1) * 16;
    const int nB  = (lane & 7) + ((lane >> 4) & 1) * 8;
    const int kBo = ((lane >> 3) & 1) * 16;

    uint32_t acc[4][8][2];
#pragma unroll
    for (int i = 0; i < 4; i++)
#pragma unroll
        for (int j = 0; j < 8; j++) { acc[i][j][0] = 0u; acc[i][j][1] = 0u; }

    auto load_stage = [&](int kt) {
        if (kt < NSTEPS) {
            const uint32_t st = sbase + (kt % NSTAGE) * STAGE;
            const size_t kOff = (size_t)kt * 128;
#pragma unroll
            for (int l = 0; l < 8; l++) {
                const int i = tid + l * 128;
                const int r = i >> 3, c = (i & 7) << 4;
                cp_async16(st + SWZ(r * 128 + c),
                           gA + (size_t)r * rowB + kOff + c);
            }
#pragma unroll
            for (int l = 0; l < 8; l++) {
                const int i = tid + l * 128;
                const int r = i >> 3, c = (i & 7) << 4;
                cp_async16(st + TILEB + SWZ(r * 128 + c),
                           gB + (size_t)r * rowB + kOff + c);
            }
        }
        cp_commit();
    };

    load_stage(0);
    load_stage(1);

    for (int kt = 0; kt < NSTEPS; kt++) {
        cp_wait<NSTAGE - 2>();
        __syncthreads();
        load_stage(kt + NSTAGE - 1);

        const uint32_t st = sbase + (kt % NSTAGE) * STAGE;
#pragma unroll
        for (int ck = 0; ck < 4; ck++) {
            const int kb = ck * 32;
            uint32_t a[4][4];
#pragma unroll
            for (int mi = 0; mi < 4; mi++)
                ldsm_x4(st + SWZ((wm + mi * 16 + mA) * 128 + kb + kAo), a[mi]);
            uint32_t b[4][4];
#pragma unroll
            for (int nb = 0; nb < 4; nb++)
                ldsm_x4(st + TILEB + SWZ((wn + nb * 16 + nB) * 128 + kb + kBo),
                        b[nb]);
#pragma unroll
            for (int mi = 0; mi < 4; mi++)
#pragma unroll
                for (int nb = 0; nb < 4; nb++)
#pragma unroll
                    for (int h = 0; h < 2; h++)
                        mma_f16h(acc[mi][nb * 2 + h], a[mi],
                                 b[nb][2 * h], b[nb][2 * h + 1]);
        }
    }

    // ---- scale (alpha = 2^-12, exact in fp16) and store ----
    const __half2 al2 = __floats2half2_rn(alpha, alpha);
    const int rq = lane >> 2, cq = (lane & 3) * 2;
#pragma unroll
    for (int mi = 0; mi < 4; mi++) {
        const int row0 = rowBase + wm + mi * 16 + rq;
#pragma unroll
        for (int nj = 0; nj < 8; nj++) {
            const int col = colBase + wn + nj * 8 + cq;
            const __half2 h0 = __hmul2(*(__half2*)&acc[mi][nj][0], al2);
            const __half2 h1 = __hmul2(*(__half2*)&acc[mi][nj][1], al2);
            *(__half2*)&C[(size_t)row0 * NMAT + col]       = h0;
            *(__half2*)&C[(size_t)(row0 + 8) * NMAT + col] = h1;
        }
    }

    // ---- mirror store (transpose via smem) for off-diagonal tiles ----
    if (blockIdx.x != blockIdx.y) {
        __syncthreads();  // all warps done reading the last stage
        float* T = (float*)smem;  // [128][TPAD] floats = 67.6 KB <= 96 KB
        const float af = alpha;
#pragma unroll
        for (int mi = 0; mi < 4; mi++) {
            const int r0 = wm + mi * 16 + rq;
#pragma unroll
            for (int nj = 0; nj < 8; nj++) {
                const int c0 = wn + nj * 8 + cq;
                const float2 f0 = __half22float2(*(__half2*)&acc[mi][nj][0]);
                const float2 f1 = __half22float2(*(__half2*)&acc[mi][nj][1]);
                T[(c0 + 0) * TPAD + r0]     = f0.x * af;
                T[(c0 + 1) * TPAD + r0]     = f0.y * af;
                T[(c0 + 0) * TPAD + r0 + 8] = f1.x * af;
                T[(c0 + 1) * TPAD + r0 + 8] = f1.y * af;
            }
        }
        __syncthreads();
#pragma unroll 4
        for (int rb = 0; rb < 128; rb += 4) {
            const int rr = rb + warp;
            const float4 v = *(const float4*)&T[rr * TPAD + (lane << 2)];
            __half2 h0 = __floats2half2_rn(v.x, v.y);
            __half2 h1 = __floats2half2_rn(v.z, v.w);
            *(uint2*)&C[(size_t)(colBase + rr) * NMAT + rowBase + (lane << 2)] =
                make_uint2(*(uint32_t*)&h0, *(uint32_t*)&h1);
        }
    }
}

// ===========================================================================
// GEMM2 (full): out = alpha * A @ B^T, fp32 accum, fp32 out.  (R8 path.)
// ===========================================================================
__global__ __launch_bounds__(128, 2)
void gemm_full(const __half* __restrict__ A, const __half* __restrict__ B,
               float* __restrict__ C, float alpha)
{
    extern __shared__ char smem[];
    const uint32_t sbase = smem_u32(smem);

    const int tid  = threadIdx.x;
    const int warp = tid >> 5;
    const int lane = tid & 31;
    const int wm   = (warp & 1) * 64;
    const int wn   = (warp >> 1) * 64;
    const int rowBase = blockIdx.y * 128;
    const int colBase = blockIdx.x * 128;

    const size_t rowB = (size_t)NMAT * 2;
    const char* gA = (const char*)(A + (size_t)rowBase * NMAT);
    const char* gB = (const char*)(B + (size_t)colBase * NMAT);

    const int mA  = (lane & 7) + ((lane >> 3) & 1) * 8;
    const int kAo = ((lane >> 4) & 1) * 16;
    const int nB  = (lane & 7) + ((lane >> 4) & 1) * 8;
    const int kBo = ((lane >> 3) & 1) * 16;

    float acc[4][8][4];
#pragma unroll
    for (int i = 0; i < 4; i++)
#pragma unroll
        for (int j = 0; j < 8; j++)
#pragma unroll
            for (int t = 0; t < 4; t++) acc[i][j][t] = 0.0f;

    auto load_stage = [&](int kt) {
        if (kt < NSTEPS) {
            const uint32_t st = sbase + (kt % NSTAGE) * STAGE;
            const size_t kOff = (size_t)kt * 128;
#pragma unroll
            for (int l = 0; l < 8; l++) {
                const int i = tid + l * 128;
                const int r = i >> 3, c = (i & 7) << 4;
                cp_async16(st + SWZ(r * 128 + c),
                           gA + (size_t)r * rowB + kOff + c);
            }
#pragma unroll
            for (int l = 0; l < 8; l++) {
                const int i = tid + l * 128;
                const int r = i >> 3, c = (i & 7) << 4;
                cp_async16(st + TILEB + SWZ(r * 128 + c),
                           gB + (size_t)r * rowB + kOff + c);
            }
        }
        cp_commit();
    };

    load_stage(0);
    load_stage(1);

    for (int kt = 0; kt < NSTEPS; kt++) {
        cp_wait<NSTAGE - 2>();
        __syncthreads();
        load_stage(kt + NSTAGE - 1);

        const uint32_t st = sbase + (kt % NSTAGE) * STAGE;
#pragma unroll
        for (int ck = 0; ck < 4; ck++) {
            const int kb = ck * 32;
            uint32_t a[4][4];
#pragma unroll
            for (int mi = 0; mi < 4; mi++)
                ldsm_x4(st + SWZ((wm + mi * 16 + mA) * 128 + kb + kAo), a[mi]);
            uint32_t b[4][4];
#pragma unroll
            for (int nb = 0; nb < 4; nb++)
                ldsm_x4(st + TILEB + SWZ((wn + nb * 16 + nB) * 128 + kb + kBo),
                        b[nb]);
#pragma unroll
            for (int mi = 0; mi < 4; mi++)
#pragma unroll
                for (int nb = 0; nb < 4; nb++)
#pragma unroll
                    for (int h = 0; h < 2; h++)
                        mma_f16(acc[mi][nb * 2 + h], a[mi],
                                b[nb][2 * h], b[nb][2 * h + 1]);
        }
    }

    const int rq = lane >> 2, cq = (lane & 3) * 2;
#pragma unroll
    for (int mi = 0; mi < 4; mi++) {
        const int row0 = rowBase + wm + mi * 16 + rq;
#pragma unroll
        for (int nj = 0; nj < 8; nj++) {
            const int col = colBase + wn + nj * 8 + cq;
            *(float2*)&C[(size_t)row0 * NMAT + col] =
                make_float2(acc[mi][nj][0] * alpha, acc[mi][nj][1] * alpha);
            *(float2*)&C[(size_t)(row0 + 8) * NMAT + col] =
                make_float2(acc[mi][nj][2] * alpha, acc[mi][nj][3] * alpha);
        }
    }
}

// ===========================================================================
// feats fp32 -> fp16
// ===========================================================================
__global__ __launch_bounds__(256)
void conv_f16(const float* __restrict__ x, __half* __restrict__ h)
{
    const size_t i = (size_t)blockIdx.x * blockDim.x + threadIdx.x;
    const float4 v = ((const float4*)x)[i];
    __half2* hp = (__half2*)h;
    hp[2 * i]     = __floats2half2_rn(v.x, v.y);
    hp[2 * i + 1] = __floats2half2_rn(v.z, v.w);
}

// ===========================================================================
// Row softmax over fp16 sims with diag mask; emits fp16 attn.
// ===========================================================================
__global__ __launch_bounds__(256)
void softmax_rows(const __half* __restrict__ S, __half* __restrict__ ah)
{
    const int row = blockIdx.x;
    const int tid = threadIdx.x;
    const __half2* p = (const __half2*)(S + (size_t)row * NMAT);

    float v[16];
    float m = -FLT_MAX;
#pragma unroll
    for (int i = 0; i < 8; i++) {
        const int j2 = tid + i * 256;
        const float2 f = __half22float2(p[j2]);
        v[2 * i] = f.x;
        v[2 * i + 1] = f.y;
        const int j = 2 * j2;
        if (j != row)     m = fmaxf(m, f.x);
        if (j + 1 != row) m = fmaxf(m, f.y);
    }

    __shared__ float red[256];
    red[tid] = m;
    __syncthreads();
#pragma unroll
    for (int s = 128; s > 0; s >>= 1) {
        if (tid < s) red[tid] = fmaxf(red[tid], red[tid + s]);
        __syncthreads();
    }
    m = red[0];
    __syncthreads();

    float sum = 0.0f;
#pragma unroll
    for (int i = 0; i < 8; i++) {
        const int j = 2 * (tid + i * 256);
        float e0 = (j == row)     ? 0.0f : __expf(v[2 * i] - m);
        float e1 = (j + 1 == row) ? 0.0f : __expf(v[2 * i + 1] - m);
        v[2 * i] = e0;
        v[2 * i + 1] = e1;
        sum += e0 + e1;
    }
    red[tid] = sum;
    __syncthreads();
#pragma unroll
    for (int s = 128; s > 0; s >>= 1) {
        if (tid < s) red[tid] += red[tid + s];
        __syncthreads();
    }
    const float inv = 1.0f / red[0];

    __half2* arow = (__half2*)(ah + (size_t)row * NMAT);
#pragma unroll
    for (int i = 0; i < 8; i++) {
        const int j2 = tid + i * 256;
        arow[j2] = __floats2half2_rn(v[2 * i] * inv, v[2 * i + 1] * inv);
    }
}

// ===========================================================================
extern "C" void kernel_launch(void* const* d_in, const int* in_sizes, int n_in,
                              void* d_out, int out_size)
{
    const float* feats = (const float*)d_in[0];
    float* out = (float*)d_out;

    __half *sims, *xh, *ah;
    cudaGetSymbolAddress((void**)&sims, g_sims);
    cudaGetSymbolAddress((void**)&xh, g_xh);
    cudaGetSymbolAddress((void**)&ah, g_ah);

    cudaFuncSetAttribute((void*)gemm_sym,
                         cudaFuncAttributeMaxDynamicSharedMemorySize, SMEM_TOTAL);
    cudaFuncSetAttribute((void*)gemm_full,
                         cudaFuncAttributeMaxDynamicSharedMemorySize, SMEM_TOTAL);

    // 1) feats -> fp16
    conv_f16<<<(NMAT * (size_t)NMAT / 4) / 256, 256>>>(feats, xh);

    dim3 grid(NMAT / 128, NMAT / 128);  // (32, 32)

    // 2) sims = feats @ feats^T / 4096  (symmetric; fp16 accum probe)
    gemm_sym<<<grid, 128, SMEM_TOTAL>>>(xh, sims, 1.0f / 4096.0f);

    // 3) softmax rows (diag masked) -> fp16 attn
    softmax_rows<<<NMAT, 256>>>(sims, ah);

    // 4) out = attn @ feats^T / 64  (fp32 accum)
    gemm_full<<<grid, 128, SMEM_TOTAL>>>(ah, xh, out, 1.0f / 64.0f);
}

// round 14
// speedup vs baseline: 3.0558x; 1.0387x over previous
#include <cuda_runtime.h>
#include <cuda_fp16.h>
#include <cfloat>
#include <cstdint>

// ===========================================================================
// SimpleAttention 4096x4096, sm_103 legacy tensor path (tcgen05 unavailable on
// the plain sm_103 PTX target; legacy s8 IMMA ~4x slow; fp16-acc rate-neutral).
//   sims = feats @ feats^T / 4096   GEMM1: fp16 in, fp32 accum, symmetric ->
//                                   upper tiles + mirror write, fp16 out.
//   attn = softmax(sims, diag masked) -> fp16
//   out  = attn @ feats^T / 64      GEMM2: fp16 in, fp32 accum, fp32 out.
// CTA tile 128x128, 8 warps (warp tile 64x32 -> 4 warps/SMSP with 2 CTA/SM),
// BK=64, 3-stage cp.async.
// ===========================================================================

constexpr int NMAT = 4096;
constexpr int NSTEPS = 64;                // 4096 / 64
constexpr int TILEB = 128 * 128;          // bytes per operand tile (128B rows)
constexpr int STAGE = 2 * TILEB;          // 32 KB
constexpr int NSTAGE = 3;                 // 96 KB smem
constexpr int SMEM_TOTAL = NSTAGE * STAGE;
constexpr int TPAD = 132;                 // transpose buffer row stride (floats)

// ---- device scratch (allocation-free) -------------------------------------
__device__ __half g_sims[(size_t)NMAT * NMAT];  // fp16 sims
__device__ __half g_xh[(size_t)NMAT * NMAT];    // fp16(feats)
__device__ __half g_ah[(size_t)NMAT * NMAT];    // fp16(attn)

// ---- helpers --------------------------------------------------------------
#define SWZ(o) ((o) ^ (((o) >> 3) & 0x70))

__device__ __forceinline__ uint32_t smem_u32(const void* p) {
    uint32_t a;
    asm("{ .reg .u64 t; cvta.to.shared.u64 t, %1; cvt.u32.u64 %0, t; }"
        : "=r"(a) : "l"(p));
    return a;
}
__device__ __forceinline__ void cp_async16(uint32_t dst, const void* src) {
    asm volatile("cp.async.cg.shared.global [%0], [%1], 16;"
                 :: "r"(dst), "l"(src));
}
__device__ __forceinline__ void cp_commit() {
    asm volatile("cp.async.commit_group;" ::: "memory");
}
template <int N>
__device__ __forceinline__ void cp_wait() {
    asm volatile("cp.async.wait_group %0;" :: "n"(N) : "memory");
}
__device__ __forceinline__ void ldsm_x4(uint32_t addr, uint32_t r[4]) {
    asm volatile("ldmatrix.sync.aligned.m8n8.x4.shared.b16 {%0,%1,%2,%3}, [%4];"
                 : "=r"(r[0]), "=r"(r[1]), "=r"(r[2]), "=r"(r[3]) : "r"(addr));
}
__device__ __forceinline__ void mma_f16(float d[4], const uint32_t a[4],
                                        uint32_t b0, uint32_t b1) {
    asm volatile(
        "mma.sync.aligned.m16n8k16.row.col.f32.f16.f16.f32 "
        "{%0,%1,%2,%3}, {%4,%5,%6,%7}, {%8,%9}, {%0,%1,%2,%3};"
        : "+f"(d[0]), "+f"(d[1]), "+f"(d[2]), "+f"(d[3])
        : "r"(a[0]), "r"(a[1]), "r"(a[2]), "r"(a[3]), "r"(b0), "r"(b1));
}

// ===========================================================================
// C[128x128] = alpha * A @ B^T, fp16 in, fp32 accum.  OutT in {float, __half}.
// 8 warps, warp tile 64x32 (wm = (warp&1)*64, wn = (warp>>1)*32).
// MIRROR: compute only by <= bx; off-diagonal tiles also written transposed.
// ===========================================================================
template <bool MIRROR, typename OutT>
__global__ __launch_bounds__(256, 2)
void gemm_f16(const __half* __restrict__ A, const __half* __restrict__ B,
              OutT* __restrict__ C, float alpha)
{
    if (MIRROR && blockIdx.y > blockIdx.x) return;

    extern __shared__ char smem[];
    const uint32_t sbase = smem_u32(smem);

    const int tid  = threadIdx.x;
    const int warp = tid >> 5;
    const int lane = tid & 31;
    const int wm   = (warp & 1) * 64;    // warp row offset
    const int wn   = (warp >> 1) * 32;   // warp col offset (0,32,64,96)
    const int rowBase = blockIdx.y * 128;
    const int colBase = blockIdx.x * 128;

    const size_t rowB = (size_t)NMAT * 2;
    const char* gA = (const char*)(A + (size_t)rowBase * NMAT);
    const char* gB = (const char*)(B + (size_t)colBase * NMAT);

    const int mA  = (lane & 7) + ((lane >> 3) & 1) * 8;
    const int kAo = ((lane >> 4) & 1) * 16;
    const int nB  = (lane & 7) + ((lane >> 4) & 1) * 8;
    const int kBo = ((lane >> 3) & 1) * 16;

    float acc[4][4][4];   // mi x nj(n8) x 4
#pragma unroll
    for (int i = 0; i < 4; i++)
#pragma unroll
        for (int j = 0; j < 4; j++)
#pragma unroll
            for (int t = 0; t < 4; t++) acc[i][j][t] = 0.0f;

    auto load_stage = [&](int kt) {
        if (kt < NSTEPS) {
            const uint32_t st = sbase + (kt % NSTAGE) * STAGE;
            const size_t kOff = (size_t)kt * 128;
#pragma unroll
            for (int l = 0; l < 4; l++) {        // A: 128 rows x 8 chunks
                const int i = tid + l * 256;
                const int r = i >> 3, c = (i & 7) << 4;
                cp_async16(st + SWZ(r * 128 + c),
                           gA + (size_t)r * rowB + kOff + c);
            }
#pragma unroll
            for (int l = 0; l < 4; l++) {        // B: 128 rows x 8 chunks
                const int i = tid + l * 256;
                const int r = i >> 3, c = (i & 7) << 4;
                cp_async16(st + TILEB + SWZ(r * 128 + c),
                           gB + (size_t)r * rowB + kOff + c);
            }
        }
        cp_commit();
    };

    load_stage(0);
    load_stage(1);

    for (int kt = 0; kt < NSTEPS; kt++) {
        cp_wait<NSTAGE - 2>();
        __syncthreads();
        load_stage(kt + NSTAGE - 1);

        const uint32_t st = sbase + (kt % NSTAGE) * STAGE;
#pragma unroll
        for (int ck = 0; ck < 4; ck++) {
            const int kb = ck * 32;
            uint32_t a[4][4];
#pragma unroll
            for (int mi = 0; mi < 4; mi++)
                ldsm_x4(st + SWZ((wm + mi * 16 + mA) * 128 + kb + kAo), a[mi]);
            uint32_t b[2][4];
#pragma unroll
            for (int nb = 0; nb < 2; nb++)
                ldsm_x4(st + TILEB + SWZ((wn + nb * 16 + nB) * 128 + kb + kBo),
                        b[nb]);
#pragma unroll
            for (int mi = 0; mi < 4; mi++)
#pragma unroll
                for (int nb = 0; nb < 2; nb++)
#pragma unroll
                    for (int h = 0; h < 2; h++)
                        mma_f16(acc[mi][nb * 2 + h], a[mi],
                                b[nb][2 * h], b[nb][2 * h + 1]);
        }
    }

    // ---- scale once ----
#pragma unroll
    for (int mi = 0; mi < 4; mi++)
#pragma unroll
        for (int nj = 0; nj < 4; nj++)
#pragma unroll
            for (int t = 0; t < 4; t++) acc[mi][nj][t] *= alpha;

    // ---- normal store ----
    const int rq = lane >> 2, cq = (lane & 3) * 2;
#pragma unroll
    for (int mi = 0; mi < 4; mi++) {
        const int row0 = rowBase + wm + mi * 16 + rq;
#pragma unroll
        for (int nj = 0; nj < 4; nj++) {
            const int col = colBase + wn + nj * 8 + cq;
            if constexpr (sizeof(OutT) == 4) {
                *(float2*)&C[(size_t)row0 * NMAT + col] =
                    make_float2(acc[mi][nj][0], acc[mi][nj][1]);
                *(float2*)&C[(size_t)(row0 + 8) * NMAT + col] =
                    make_float2(acc[mi][nj][2], acc[mi][nj][3]);
            } else {
                *(__half2*)&C[(size_t)row0 * NMAT + col] =
                    __floats2half2_rn(acc[mi][nj][0], acc[mi][nj][1]);
                *(__half2*)&C[(size_t)(row0 + 8) * NMAT + col] =
                    __floats2half2_rn(acc[mi][nj][2], acc[mi][nj][3]);
            }
        }
    }

    // ---- mirror store (transpose via smem) for off-diagonal tiles ----
    if (MIRROR && blockIdx.x != blockIdx.y) {
        __syncthreads();  // all warps done reading the last stage
        float* T = (float*)smem;  // [128][TPAD] floats = 67.6 KB <= 96 KB
#pragma unroll
        for (int mi = 0; mi < 4; mi++) {
            const int r0 = wm + mi * 16 + rq;
#pragma unroll
            for (int nj = 0; nj < 4; nj++) {
                const int c0 = wn + nj * 8 + cq;
                T[(c0 + 0) * TPAD + r0]     = acc[mi][nj][0];
                T[(c0 + 1) * TPAD + r0]     = acc[mi][nj][1];
                T[(c0 + 0) * TPAD + r0 + 8] = acc[mi][nj][2];
                T[(c0 + 1) * TPAD + r0 + 8] = acc[mi][nj][3];
            }
        }
        __syncthreads();
#pragma unroll 4
        for (int rb = 0; rb < 128; rb += 8) {
            const int rr = rb + warp;
            const float4 v = *(const float4*)&T[rr * TPAD + (lane << 2)];
            if constexpr (sizeof(OutT) == 4) {
                *(float4*)&C[(size_t)(colBase + rr) * NMAT + rowBase + (lane << 2)] = v;
            } else {
                __half2 h0 = __floats2half2_rn(v.x, v.y);
                __half2 h1 = __floats2half2_rn(v.z, v.w);
                *(uint2*)&C[(size_t)(colBase + rr) * NMAT + rowBase + (lane << 2)] =
                    make_uint2(*(uint32_t*)&h0, *(uint32_t*)&h1);
            }
        }
    }
}

// ===========================================================================
// feats fp32 -> fp16
// ===========================================================================
__global__ __launch_bounds__(256)
void conv_f16(const float* __restrict__ x, __half* __restrict__ h)
{
    const size_t i = (size_t)blockIdx.x * blockDim.x + threadIdx.x;
    const float4 v = ((const float4*)x)[i];
    __half2* hp = (__half2*)h;
    hp[2 * i]     = __floats2half2_rn(v.x, v.y);
    hp[2 * i + 1] = __floats2half2_rn(v.z, v.w);
}

// ===========================================================================
// Row softmax over fp16 sims with diag mask; emits fp16 attn.
// ===========================================================================
__global__ __launch_bounds__(256)
void softmax_rows(const __half* __restrict__ S, __half* __restrict__ ah)
{
    const int row = blockIdx.x;
    const int tid = threadIdx.x;
    const __half2* p = (const __half2*)(S + (size_t)row * NMAT);

    float v[16];
    float m = -FLT_MAX;
#pragma unroll
    for (int i = 0; i < 8; i++) {
        const int j2 = tid + i * 256;
        const float2 f = __half22float2(p[j2]);
        v[2 * i] = f.x;
        v[2 * i + 1] = f.y;
        const int j = 2 * j2;
        if (j != row)     m = fmaxf(m, f.x);
        if (j + 1 != row) m = fmaxf(m, f.y);
    }

    __shared__ float red[256];
    red[tid] = m;
    __syncthreads();
#pragma unroll
    for (int s = 128; s > 0; s >>= 1) {
        if (tid < s) red[tid] = fmaxf(red[tid], red[tid + s]);
        __syncthreads();
    }
    m = red[0];
    __syncthreads();

    float sum = 0.0f;
#pragma unroll
    for (int i = 0; i < 8; i++) {
        const int j = 2 * (tid + i * 256);
        float e0 = (j == row)     ? 0.0f : __expf(v[2 * i] - m);
        float e1 = (j + 1 == row) ? 0.0f : __expf(v[2 * i + 1] - m);
        v[2 * i] = e0;
        v[2 * i + 1] = e1;
        sum += e0 + e1;
    }
    red[tid] = sum;
    __syncthreads();
#pragma unroll
    for (int s = 128; s > 0; s >>= 1) {
        if (tid < s) red[tid] += red[tid + s];
        __syncthreads();
    }
    const float inv = 1.0f / red[0];

    __half2* arow = (__half2*)(ah + (size_t)row * NMAT);
#pragma unroll
    for (int i = 0; i < 8; i++) {
        const int j2 = tid + i * 256;
        arow[j2] = __floats2half2_rn(v[2 * i] * inv, v[2 * i + 1] * inv);
    }
}

// ===========================================================================
extern "C" void kernel_launch(void* const* d_in, const int* in_sizes, int n_in,
                              void* d_out, int out_size)
{
    const float* feats = (const float*)d_in[0];
    float* out = (float*)d_out;

    __half *sims, *xh, *ah;
    cudaGetSymbolAddress((void**)&sims, g_sims);
    cudaGetSymbolAddress((void**)&xh, g_xh);
    cudaGetSymbolAddress((void**)&ah, g_ah);

    cudaFuncSetAttribute((void*)gemm_f16<true, __half>,
                         cudaFuncAttributeMaxDynamicSharedMemorySize, SMEM_TOTAL);
    cudaFuncSetAttribute((void*)gemm_f16<false, float>,
                         cudaFuncAttributeMaxDynamicSharedMemorySize, SMEM_TOTAL);

    // 1) feats -> fp16
    conv_f16<<<(NMAT * (size_t)NMAT / 4) / 256, 256>>>(feats, xh);

    dim3 grid(NMAT / 128, NMAT / 128);  // (32, 32)

    // 2) sims = feats @ feats^T / 4096  (symmetric: upper tiles + mirror)
    gemm_f16<true, __half><<<grid, 256, SMEM_TOTAL>>>(xh, xh, sims, 1.0f / 4096.0f);

    // 3) softmax rows (diag masked) -> fp16 attn
    softmax_rows<<<NMAT, 256>>>(sims, ah);

    // 4) out = attn @ feats^T / 64
    gemm_f16<false, float><<<grid, 256, SMEM_TOTAL>>>(ah, xh, out, 1.0f / 64.0f);
}